// round 5
// baseline (speedup 1.0000x reference)
#include <cuda_runtime.h>
#include <cuda_fp16.h>
#include <math.h>
#include <stdint.h>

#define B 32
#define C 128
#define L 4096
#define NROW (B*C)
#define BCL (B*C*L)            // 16777216
#define FL 9
#define DIM 512
#define NYL ((size_t)BCL)

// ---------------- scratch (device globals; no allocation) ----------------
__device__ float g_a1[BCL];
__device__ float g_a2[BCL];
__device__ float g_a3[BCL];
__device__ float g_attn[B*(C/4)*L];
__device__ float g_feat[B*C];
__device__ __half g_wf[3*C*384];     // [lvl][co][k=tap*128+ci] fp16

__device__ __forceinline__ float gelu_f(float x){
    return 0.5f*x*(1.0f+erff(x*0.7071067811865476f));
}
__device__ __forceinline__ float sigmoid_f(float x){
    return 1.0f/(1.0f+expf(-x));
}

// ---- packed f32x2 helpers (Blackwell FFMA2) ----
__device__ __forceinline__ unsigned long long pack2(float lo, float hi){
    unsigned long long r;
    asm("mov.b64 %0, {%1, %2};" : "=l"(r) : "f"(lo), "f"(hi));
    return r;
}
__device__ __forceinline__ unsigned long long fma2(unsigned long long a, unsigned long long b, unsigned long long c){
    unsigned long long d;
    asm("fma.rn.f32x2 %0, %1, %2, %3;" : "=l"(d) : "l"(a), "l"(b), "l"(c));
    return d;
}
__device__ __forceinline__ float2 unpack2(unsigned long long v){
    float2 f;
    asm("mov.b64 {%0, %1}, %2;" : "=f"(f.x), "=f"(f.y) : "l"(v));
    return f;
}

// ---- smem addr + mma.sync helpers (baseline PTX, no sm_103a-gated features) ----
__device__ __forceinline__ uint32_t smem_u32(const void* p){
    uint32_t a;
    asm("{ .reg .u64 t; cvta.to.shared.u64 t, %1; cvt.u32.u64 %0, t; }" : "=r"(a) : "l"(p));
    return a;
}
__device__ __forceinline__ void ldsm_x4(uint32_t* r, uint32_t addr){
    asm volatile("ldmatrix.sync.aligned.m8n8.x4.shared.b16 {%0,%1,%2,%3}, [%4];"
        : "=r"(r[0]), "=r"(r[1]), "=r"(r[2]), "=r"(r[3]) : "r"(addr));
}
__device__ __forceinline__ void mma_16816(float* c, const uint32_t* a, uint32_t b0, uint32_t b1){
    asm volatile("mma.sync.aligned.m16n8k16.row.col.f32.f16.f16.f32 "
        "{%0,%1,%2,%3}, {%4,%5,%6,%7}, {%8,%9}, {%0,%1,%2,%3};"
        : "+f"(c[0]), "+f"(c[1]), "+f"(c[2]), "+f"(c[3])
        : "r"(a[0]), "r"(a[1]), "r"(a[2]), "r"(a[3]), "r"(b0), "r"(b1));
}

// ---------------- mean over L ----------------
__global__ __launch_bounds__(256) void mean_kernel(const float* __restrict__ x,
                                                   float* __restrict__ feat){
    int row = blockIdx.x;
    const float4* p = (const float4*)(x + (size_t)row*L);
    float s = 0.f;
    for (int i = threadIdx.x; i < L/4; i += 256){
        float4 v = p[i];
        s += (v.x+v.y)+(v.z+v.w);
    }
    __shared__ float red[256];
    red[threadIdx.x] = s; __syncthreads();
    for (int off = 128; off > 0; off >>= 1){
        if (threadIdx.x < off) red[threadIdx.x] += red[threadIdx.x+off];
        __syncthreads();
    }
    if (threadIdx.x == 0) feat[row] = red[0] * (1.0f/(float)L);
}

// ---------------- fused MLP: feat->512->1024->18, write lo/hi ----------------
__global__ __launch_bounds__(512) void mlp_kernel(
    const float* __restrict__ feat,
    const float* __restrict__ stat_w, const float* __restrict__ stat_b,
    const float* __restrict__ wg1_w,  const float* __restrict__ wg1_b,
    const float* __restrict__ wg2_w,  const float* __restrict__ wg2_b,
    float* __restrict__ lo_out, float* __restrict__ hi_out)
{
    __shared__ float s_feat[C];
    __shared__ float s_h1[DIM];
    __shared__ float s_h2[2*DIM];
    int b = blockIdx.x, t = threadIdx.x;
    if (t < C) s_feat[t] = feat[b*C + t];
    __syncthreads();
    {
        float acc = stat_b[t];
        const float4* wr = (const float4*)(stat_w + (size_t)t*C);
        #pragma unroll 8
        for (int c = 0; c < C/4; c++){
            float4 w4 = wr[c];
            acc += w4.x*s_feat[4*c] + w4.y*s_feat[4*c+1] + w4.z*s_feat[4*c+2] + w4.w*s_feat[4*c+3];
        }
        s_h1[t] = gelu_f(acc);
    }
    __syncthreads();
    #pragma unroll
    for (int rep = 0; rep < 2; rep++){
        int j = t + rep*DIM;
        float acc = wg1_b[j];
        const float4* wr = (const float4*)(wg1_w + (size_t)j*DIM);
        #pragma unroll 8
        for (int c = 0; c < DIM/4; c++){
            float4 w4 = wr[c];
            acc += w4.x*s_h1[4*c] + w4.y*s_h1[4*c+1] + w4.z*s_h1[4*c+2] + w4.w*s_h1[4*c+3];
        }
        s_h2[j] = gelu_f(acc);
    }
    __syncthreads();
    if (t < 2*FL){
        float acc = wg2_b[t];
        const float4* wr = (const float4*)(wg2_w + (size_t)t*(2*DIM));
        #pragma unroll 8
        for (int c = 0; c < 2*DIM/4; c++){
            float4 w4 = wr[c];
            acc += w4.x*s_h2[4*c] + w4.y*s_h2[4*c+1] + w4.z*s_h2[4*c+2] + w4.w*s_h2[4*c+3];
        }
        if (t < FL) lo_out[b*FL + t]        = acc;
        else        hi_out[b*FL + (t-FL)]   = acc;
    }
}

// ---------------- ortho loss (last level only) + energy=0 ----------------
__global__ void ortho_kernel(const float* __restrict__ lo, float* __restrict__ out_scalars){
    int b = threadIdx.x;
    float v[FL]; float ss = 0.f;
    #pragma unroll
    for (int k = 0; k < FL; k++){ v[k] = lo[b*FL+k]; ss += v[k]*v[k]; }
    float den = sqrtf(ss) + 1e-8f;
    float S = 0.f, sq = 0.f;
    #pragma unroll
    for (int k = 0; k < FL; k++){
        float n = v[k]/den;
        S  += fabsf(n);
        sq += n*n;
    }
    float S2  = S*S;
    float amp = fabsf(sq - 1.0f);
    float sm  = fabsf(v[0]);
    #pragma unroll
    for (int k = 1; k < FL; k++) sm += fabsf(v[k]-v[k-1]);
    sm += fabsf(v[FL-1]);
    #pragma unroll
    for (int off = 16; off > 0; off >>= 1){
        S2  += __shfl_xor_sync(0xffffffffu, S2,  off);
        amp += __shfl_xor_sync(0xffffffffu, amp, off);
        sm  += __shfl_xor_sync(0xffffffffu, sm,  off);
    }
    if (b == 0){
        float shift  = 3.0f * S2 / (32.0f*81.0f);
        float ampm   = amp / 32.0f;
        float smm    = sm / (32.0f*10.0f);
        out_scalars[0] = 0.01f*(shift + ampm) + 0.1f*smm;
        out_scalars[1] = 0.0f;
    }
}

// ---------------- per-sample depthwise 9-tap (edge pad), lo+hi fused, vectorized ----------------
#define DTL 1024
__global__ __launch_bounds__(256) void dw_kernel(
    const float* __restrict__ x, const float* __restrict__ lo, const float* __restrict__ hi,
    float* __restrict__ out_a, float* __restrict__ out_d)
{
    int row = blockIdx.y;
    int b   = row >> 7;
    int l0  = blockIdx.x * DTL;
    __shared__ __align__(16) float s[DTL + 16];
    const float* xr = x + (size_t)row * L;
    int t = threadIdx.x;
    {
        const float4* xv = (const float4*)(xr + l0);
        ((float4*)(s + 4))[t] = xv[t];
    }
    if (t < 4){
        int li = l0 - 4 + t;
        s[t] = xr[max(li, 0)];
        int ri = l0 + DTL + t;
        s[DTL + 4 + t] = xr[min(ri, L-1)];
    }
    unsigned long long pf[FL];
    #pragma unroll
    for (int k = 0; k < FL; k++) pf[k] = pack2(__ldg(&lo[b*FL+k]), __ldg(&hi[b*FL+k]));
    __syncthreads();

    int i0 = t * 4;
    float win[12];
    #pragma unroll
    for (int j = 0; j < 12; j++) win[j] = s[i0 + j];
    unsigned long long acc[4];
    #pragma unroll
    for (int p = 0; p < 4; p++) acc[p] = 0ull;
    #pragma unroll
    for (int k = 0; k < FL; k++){
        #pragma unroll
        for (int p = 0; p < 4; p++){
            unsigned long long vv = pack2(win[p+k], win[p+k]);
            acc[p] = fma2(vv, pf[k], acc[p]);
        }
    }
    float4 ra, rd;
    float2 f0 = unpack2(acc[0]), f1 = unpack2(acc[1]), f2 = unpack2(acc[2]), f3 = unpack2(acc[3]);
    ra.x = f0.x; ra.y = f1.x; ra.z = f2.x; ra.w = f3.x;
    rd.x = f0.y; rd.y = f1.y; rd.z = f2.y; rd.w = f3.y;
    size_t idx = (size_t)row*L + l0 + i0;
    *(float4*)(out_a + idx) = ra;
    *(float4*)(out_d + idx) = rd;
}

// ---------------- weight prep: gates_w [lvl][co][ci][tap] -> fp16 [lvl][co][k=tap*128+ci] ----
__global__ void wprep_kernel(const float* __restrict__ gw, __half* __restrict__ wf){
    int idx = blockIdx.x*256 + threadIdx.x;
    if (idx < 3*C*384){
        int lvl = idx / (C*384);
        int r   = idx % (C*384);
        int co  = r / 384;
        int k   = r % 384;
        int tap = k >> 7, ci = k & 127;
        wf[idx] = __float2half(gw[(((size_t)lvl*C + co)*C + ci)*3 + tap]);
    }
}

// ---------------- gates conv via mma.sync fp16 ----------------
// D[l=128, co=128] = A[l, K=384] * W[K, co],  K = tap*128+ci, A[l][k] = x[ci][l0+l+tap-1] (zero pad)
// out = cur + sigmoid(D + bias) * det
#define KP 392                               // fp16 pitch (784B, %128 = 16 -> conflict-free ldmatrix)
#define PL 133                               // stage pitch (floats), gcd(133,32)=1
#define SW_OFF (128*KP*2)                    // 100352
#define GSM_TOTAL (2*128*KP*2)               // 200704

__global__ __launch_bounds__(256) void gates_mma_kernel(
    const float* __restrict__ cur, const float* __restrict__ det,
    const __half* __restrict__ wf, const float* __restrict__ bias,
    float* __restrict__ out)
{
    extern __shared__ char smem[];
    uint32_t sa_base = smem_u32(smem);
    uint32_t sw_base = sa_base + SW_OFF;
    __half* s_a = (__half*)smem;
    float*  s_d = (float*)smem;              // stage reuses A region (68KB <= 100KB)
    int t = threadIdx.x, wid = t >> 5, lane = t & 31;

    // load W once: 128 co x 384 k as u32 pairs (src row 192 u32, dst row 196 u32)
    {
        const uint32_t* src = (const uint32_t*)wf;
        uint32_t* dst = (uint32_t*)(smem + SW_OFF);
        for (int idx = t; idx < 128*192; idx += 256){
            int co = idx / 192, j = idx % 192;
            dst[co*196 + j] = src[idx];
        }
    }

    // ldmatrix lane address bases
    int a_l  = wid*16 + (lane & 15);
    int a_kh = lane >> 4;                                  // 0/1 -> k+8
    uint32_t a_base = sa_base + (uint32_t)(a_l*KP + a_kh*8)*2;

    int b_r  = lane & 7;
    int b_kh = (lane >> 3) & 1;
    int b_h8 = (lane >> 4) & 1;
    uint32_t b_base = sw_base + (uint32_t)((b_h8*8 + b_r)*KP + b_kh*8)*2;

    __syncthreads();

    for (int tile = blockIdx.x; tile < 1024; tile += gridDim.x){
        int b  = tile >> 5;                  // L/128 = 32 tiles per batch row
        int l0 = (tile & 31) << 7;
        // ---- fill A (tap-gathered fp16, zero pad at sequence edges) ----
        for (int idx = t; idx < C*130; idx += 256){
            int ci = idx / 130, jj = idx % 130;            // jj: window pos l0-1 .. l0+128
            int jl = l0 - 1 + jj;
            float v = 0.f;
            if (jl >= 0 && jl < L) v = cur[((size_t)(b*C + ci))*L + jl];
            __half h = __float2half(v);
            #pragma unroll
            for (int tp = 0; tp < 3; tp++){
                int l = jj - tp;
                if (l >= 0 && l < 128) s_a[l*KP + tp*128 + ci] = h;
            }
        }
        __syncthreads();
        // ---- mma: each warp: 16 l-rows x all 128 co ----
        float acc[16][4];
        #pragma unroll
        for (int n = 0; n < 16; n++){
            acc[n][0] = 0.f; acc[n][1] = 0.f; acc[n][2] = 0.f; acc[n][3] = 0.f;
        }
        uint32_t a_addr = a_base;
        #pragma unroll 1
        for (int ks = 0; ks < 24; ks++){
            uint32_t ra[4];
            ldsm_x4(ra, a_addr);
            a_addr += 32;                                  // k += 16 (fp16)
            uint32_t b_addr = b_base + ks*32;
            #pragma unroll
            for (int nt2 = 0; nt2 < 8; nt2++){
                uint32_t rb[4];
                ldsm_x4(rb, b_addr);
                b_addr += 16*KP*2;                         // next 16 co
                mma_16816(acc[nt2*2],     ra, rb[0], rb[1]);
                mma_16816(acc[nt2*2 + 1], ra, rb[2], rb[3]);
            }
        }
        __syncthreads();                                   // all A reads done; reuse as stage
        // ---- stage D to smem [l][co], pitch PL ----
        {
            int dl = wid*16 + (lane >> 2);
            int dc = (lane & 3)*2;
            #pragma unroll
            for (int nt = 0; nt < 16; nt++){
                s_d[dl*PL + nt*8 + dc]         = acc[nt][0];
                s_d[dl*PL + nt*8 + dc + 1]     = acc[nt][1];
                s_d[(dl+8)*PL + nt*8 + dc]     = acc[nt][2];
                s_d[(dl+8)*PL + nt*8 + dc + 1] = acc[nt][3];
            }
        }
        __syncthreads();
        // ---- fused gate + coalesced write ----
        for (int idx = t; idx < C*128; idx += 256){
            int co = idx >> 7, j = idx & 127;
            size_t g = ((size_t)(b*C + co))*L + l0 + j;
            float z = s_d[j*PL + co] + __ldg(&bias[co]);
            out[g] = cur[g] + sigmoid_f(z)*det[g];
        }
        __syncthreads();
    }
}

// ---------------- attn1: 1x1 conv 128->32 + gelu (FFMA2) ----------------
__global__ __launch_bounds__(256) void attn1_kernel(
    const float* __restrict__ cur, const float* __restrict__ w,
    const float* __restrict__ bias, float* __restrict__ outa)
{
    __shared__ __align__(16) float s_x[32*128];
    __shared__ __align__(16) float s_w[128*32];
    int b = blockIdx.y, l0 = blockIdx.x*128, t = threadIdx.x;
    for (int idx = t; idx < C*32; idx += 256){
        int ci = idx >> 5, co = idx & 31;
        s_w[idx] = w[co*C + ci];
    }
    int wid = t >> 5, lane = t & 31, co0 = wid*4;
    unsigned long long acc[2][4];
    #pragma unroll
    for (int c = 0; c < 2; c++)
        #pragma unroll
        for (int j = 0; j < 4; j++) acc[c][j] = 0ull;

    for (int ci0 = 0; ci0 < C; ci0 += 32){
        __syncthreads();
        for (int idx = t; idx < 32*128; idx += 256){
            int ci = idx >> 7, l = idx & 127;
            s_x[idx] = cur[((size_t)(b*C + ci0 + ci))*L + l0 + l];
        }
        __syncthreads();
        #pragma unroll 4
        for (int ci = 0; ci < 32; ci++){
            unsigned long long wr[2];
            wr[0] = *(const unsigned long long*)(&s_w[(ci0+ci)*32 + co0]);
            wr[1] = *(const unsigned long long*)(&s_w[(ci0+ci)*32 + co0 + 2]);
            #pragma unroll
            for (int j = 0; j < 4; j++){
                float xv = s_x[ci*128 + lane + j*32];
                unsigned long long p = pack2(xv, xv);
                acc[0][j] = fma2(wr[0], p, acc[0][j]);
                acc[1][j] = fma2(wr[1], p, acc[1][j]);
            }
        }
    }
    #pragma unroll
    for (int c = 0; c < 2; c++){
        int co = co0 + 2*c;
        float b0 = bias[co], b1 = bias[co+1];
        #pragma unroll
        for (int j = 0; j < 4; j++){
            float2 f = unpack2(acc[c][j]);
            size_t idx0 = ((size_t)(b*32 + co))*L + l0 + lane + j*32;
            outa[idx0]     = gelu_f(f.x + b0);
            outa[idx0 + L] = gelu_f(f.y + b1);
        }
    }
}

// ---------------- attn2: 1x1 conv 32->128 + sigmoid; det *= (1+attn) (FFMA2) ----------------
__global__ __launch_bounds__(256) void attn2_kernel(
    const float* __restrict__ a, const float* __restrict__ w,
    const float* __restrict__ bias, float* __restrict__ det)
{
    __shared__ __align__(16) float s_x[32*128];
    __shared__ __align__(16) float s_w[32*132];
    int b = blockIdx.y, l0 = blockIdx.x*128, t = threadIdx.x;
    for (int idx = t; idx < 32*128; idx += 256){
        int ci = idx >> 7, l = idx & 127;
        s_x[idx] = a[((size_t)(b*32 + ci))*L + l0 + l];
    }
    for (int idx = t; idx < C*32; idx += 256){
        int ci = idx >> 7, co = idx & 127;
        s_w[ci*132 + co] = w[co*32 + ci];
    }
    __syncthreads();
    int wid = t >> 5, lane = t & 31, co0 = wid*16;
    unsigned long long acc[8][4];
    #pragma unroll
    for (int c = 0; c < 8; c++)
        #pragma unroll
        for (int j = 0; j < 4; j++) acc[c][j] = 0ull;
    #pragma unroll 2
    for (int ci = 0; ci < 32; ci++){
        unsigned long long wr[8];
        const ulonglong2* wp = (const ulonglong2*)(&s_w[ci*132 + co0]);
        ((ulonglong2*)wr)[0] = wp[0];
        ((ulonglong2*)wr)[1] = wp[1];
        ((ulonglong2*)wr)[2] = wp[2];
        ((ulonglong2*)wr)[3] = wp[3];
        #pragma unroll
        for (int j = 0; j < 4; j++){
            float xv = s_x[ci*128 + lane + j*32];
            unsigned long long p = pack2(xv, xv);
            #pragma unroll
            for (int c = 0; c < 8; c++)
                acc[c][j] = fma2(wr[c], p, acc[c][j]);
        }
    }
    #pragma unroll
    for (int c = 0; c < 8; c++){
        int co = co0 + 2*c;
        float b0 = bias[co], b1 = bias[co+1];
        #pragma unroll
        for (int j = 0; j < 4; j++){
            float2 f = unpack2(acc[c][j]);
            size_t idx0 = ((size_t)(b*C+co))*L + l0 + lane + j*32;
            size_t idx1 = idx0 + L;
            det[idx0] = det[idx0]*(1.0f + sigmoid_f(f.x + b0));
            det[idx1] = det[idx1]*(1.0f + sigmoid_f(f.y + b1));
        }
    }
}

// ---------------- host launch ----------------
extern "C" void kernel_launch(void* const* d_in, const int* in_sizes, int n_in,
                              void* d_out, int out_size)
{
    const float* x       = (const float*)d_in[0];
    const float* stat_w  = (const float*)d_in[1];
    const float* stat_b  = (const float*)d_in[2];
    const float* wg1_w   = (const float*)d_in[3];
    const float* wg1_b   = (const float*)d_in[4];
    const float* wg2_w   = (const float*)d_in[5];
    const float* wg2_b   = (const float*)d_in[6];
    const float* gates_w = (const float*)d_in[7];
    const float* gates_b = (const float*)d_in[8];
    const float* attn1_w = (const float*)d_in[9];
    const float* attn1_b = (const float*)d_in[10];
    const float* attn2_w = (const float*)d_in[11];
    const float* attn2_b = (const float*)d_in[12];
    float* out = (float*)d_out;

    float *a1, *a2, *a3, *attn, *feat;
    __half *wf;
    cudaGetSymbolAddress((void**)&a1,   g_a1);
    cudaGetSymbolAddress((void**)&a2,   g_a2);
    cudaGetSymbolAddress((void**)&a3,   g_a3);
    cudaGetSymbolAddress((void**)&attn, g_attn);
    cudaGetSymbolAddress((void**)&feat, g_feat);
    cudaGetSymbolAddress((void**)&wf,   g_wf);

    float* yl  = out;
    float* yh0 = out + NYL;
    float* yh1 = out + 2*NYL;
    float* yh2 = out + 3*NYL;
    float* scal= out + 4*NYL;
    float* lo_all = out + 4*NYL + 2;
    float* hi_all = lo_all + 3*B*FL;

    static int smem_set = 0;
    if (!smem_set){
        cudaFuncSetAttribute(gates_mma_kernel, cudaFuncAttributeMaxDynamicSharedMemorySize, GSM_TOTAL);
        smem_set = 1;
    }

    wprep_kernel<<<(3*C*384 + 255)/256, 256>>>(gates_w, wf);

    const float* ain[3]  = {x, a1, a2};
    float*       aout[3] = {a1, a2, a3};
    float*       dets[3] = {yh0, yh1, yh2};

    for (int lvl = 0; lvl < 3; lvl++){
        float* lo = lo_all + lvl*B*FL;
        float* hi = hi_all + lvl*B*FL;
        mean_kernel<<<NROW, 256>>>(ain[lvl], feat);
        mlp_kernel<<<B, 512>>>(feat, stat_w, stat_b, wg1_w, wg1_b, wg2_w, wg2_b, lo, hi);
        dw_kernel<<<dim3(L/DTL, NROW), 256>>>(ain[lvl], lo, hi, aout[lvl], dets[lvl]);
    }

    ortho_kernel<<<1, 32>>>(lo_all + 2*B*FL, scal);

    // reconstruction: i = 2 (no attn)
    gates_mma_kernel<<<152, 256, GSM_TOTAL>>>(a3, yh2, wf + 2*C*384, gates_b + 2*C, a1);
    // i = 1
    attn1_kernel<<<dim3(L/128, B), 256>>>(a1, attn1_w + 1*(C/4)*C, attn1_b + (C/4), attn);
    attn2_kernel<<<dim3(L/128, B), 256>>>(attn, attn2_w + 1*C*(C/4), attn2_b + C, yh1);
    gates_mma_kernel<<<152, 256, GSM_TOTAL>>>(a1, yh1, wf + 1*C*384, gates_b + 1*C, a2);
    // i = 0
    attn1_kernel<<<dim3(L/128, B), 256>>>(a2, attn1_w, attn1_b, attn);
    attn2_kernel<<<dim3(L/128, B), 256>>>(attn, attn2_w, attn2_b, yh0);
    gates_mma_kernel<<<152, 256, GSM_TOTAL>>>(a2, yh0, wf, gates_b, yl);
}

// round 6
// speedup vs baseline: 1.0770x; 1.0770x over previous
#include <cuda_runtime.h>
#include <math.h>
#include <stdint.h>

#define B 32
#define C 128
#define L 4096
#define NROW (B*C)
#define BCL (B*C*L)            // 16777216
#define FL 9
#define DIM 512
#define NYL ((size_t)BCL)

// ---------------- scratch (device globals; no allocation) ----------------
__device__ float g_a1[BCL];
__device__ float g_a2[BCL];
__device__ float g_a3[BCL];
__device__ float g_attn[B*(C/4)*L];
__device__ float g_feat[3*B*C];          // per-level feature means
__device__ float g_wt[3*C*3*C];          // gates weights [lvl][ci][k][co]
__device__ float g_w2t[2*32*C];          // attn2 weights [lvl][ci][co]

__device__ __forceinline__ float gelu_f(float x){
    return 0.5f*x*(1.0f+erff(x*0.7071067811865476f));
}
__device__ __forceinline__ float sigmoid_f(float x){
    return 1.0f/(1.0f+expf(-x));
}

// ---- packed f32x2 helpers (Blackwell FFMA2) ----
__device__ __forceinline__ unsigned long long pack2(float lo, float hi){
    unsigned long long r;
    asm("mov.b64 %0, {%1, %2};" : "=l"(r) : "f"(lo), "f"(hi));
    return r;
}
__device__ __forceinline__ unsigned long long fma2(unsigned long long a, unsigned long long b, unsigned long long c){
    unsigned long long d;
    asm("fma.rn.f32x2 %0, %1, %2, %3;" : "=l"(d) : "l"(a), "l"(b), "l"(c));
    return d;
}
__device__ __forceinline__ float2 unpack2(unsigned long long v){
    float2 f;
    asm("mov.b64 {%0, %1}, %2;" : "=f"(f.x), "=f"(f.y) : "l"(v));
    return f;
}

// ---------------- mean over L (level 0 only) ----------------
__global__ __launch_bounds__(256) void mean_kernel(const float* __restrict__ x,
                                                   float* __restrict__ feat){
    int row = blockIdx.x;
    const float4* p = (const float4*)(x + (size_t)row*L);
    float s = 0.f;
    for (int i = threadIdx.x; i < L/4; i += 256){
        float4 v = p[i];
        s += (v.x+v.y)+(v.z+v.w);
    }
    __shared__ float red[256];
    red[threadIdx.x] = s; __syncthreads();
    for (int off = 128; off > 0; off >>= 1){
        if (threadIdx.x < off) red[threadIdx.x] += red[threadIdx.x+off];
        __syncthreads();
    }
    if (threadIdx.x == 0) feat[row] = red[0] * (1.0f/(float)L);
}

// ---------------- fused MLP: feat->512->1024->18, write lo/hi ----------------
__global__ __launch_bounds__(512) void mlp_kernel(
    const float* __restrict__ feat,
    const float* __restrict__ stat_w, const float* __restrict__ stat_b,
    const float* __restrict__ wg1_w,  const float* __restrict__ wg1_b,
    const float* __restrict__ wg2_w,  const float* __restrict__ wg2_b,
    float* __restrict__ lo_out, float* __restrict__ hi_out)
{
    __shared__ float s_feat[C];
    __shared__ float s_h1[DIM];
    __shared__ float s_h2[2*DIM];
    int b = blockIdx.x, t = threadIdx.x;
    if (t < C) s_feat[t] = feat[b*C + t];
    __syncthreads();
    {
        float acc = stat_b[t];
        const float4* wr = (const float4*)(stat_w + (size_t)t*C);
        #pragma unroll 8
        for (int c = 0; c < C/4; c++){
            float4 w4 = wr[c];
            acc += w4.x*s_feat[4*c] + w4.y*s_feat[4*c+1] + w4.z*s_feat[4*c+2] + w4.w*s_feat[4*c+3];
        }
        s_h1[t] = gelu_f(acc);
    }
    __syncthreads();
    #pragma unroll
    for (int rep = 0; rep < 2; rep++){
        int j = t + rep*DIM;
        float acc = wg1_b[j];
        const float4* wr = (const float4*)(wg1_w + (size_t)j*DIM);
        #pragma unroll 8
        for (int c = 0; c < DIM/4; c++){
            float4 w4 = wr[c];
            acc += w4.x*s_h1[4*c] + w4.y*s_h1[4*c+1] + w4.z*s_h1[4*c+2] + w4.w*s_h1[4*c+3];
        }
        s_h2[j] = gelu_f(acc);
    }
    __syncthreads();
    if (t < 2*FL){
        float acc = wg2_b[t];
        const float4* wr = (const float4*)(wg2_w + (size_t)t*(2*DIM));
        #pragma unroll 8
        for (int c = 0; c < 2*DIM/4; c++){
            float4 w4 = wr[c];
            acc += w4.x*s_h2[4*c] + w4.y*s_h2[4*c+1] + w4.z*s_h2[4*c+2] + w4.w*s_h2[4*c+3];
        }
        if (t < FL) lo_out[b*FL + t]        = acc;
        else        hi_out[b*FL + (t-FL)]   = acc;
    }
}

// ---------------- ortho loss (last level only) + energy=0 ----------------
__global__ void ortho_kernel(const float* __restrict__ lo, float* __restrict__ out_scalars){
    int b = threadIdx.x;
    float v[FL]; float ss = 0.f;
    #pragma unroll
    for (int k = 0; k < FL; k++){ v[k] = lo[b*FL+k]; ss += v[k]*v[k]; }
    float den = sqrtf(ss) + 1e-8f;
    float S = 0.f, sq = 0.f;
    #pragma unroll
    for (int k = 0; k < FL; k++){
        float n = v[k]/den;
        S  += fabsf(n);
        sq += n*n;
    }
    float S2  = S*S;
    float amp = fabsf(sq - 1.0f);
    float sm  = fabsf(v[0]);
    #pragma unroll
    for (int k = 1; k < FL; k++) sm += fabsf(v[k]-v[k-1]);
    sm += fabsf(v[FL-1]);
    #pragma unroll
    for (int off = 16; off > 0; off >>= 1){
        S2  += __shfl_xor_sync(0xffffffffu, S2,  off);
        amp += __shfl_xor_sync(0xffffffffu, amp, off);
        sm  += __shfl_xor_sync(0xffffffffu, sm,  off);
    }
    if (b == 0){
        float shift  = 3.0f * S2 / (32.0f*81.0f);
        float ampm   = amp / 32.0f;
        float smm    = sm / (32.0f*10.0f);
        out_scalars[0] = 0.01f*(shift + ampm) + 0.1f*smm;
        out_scalars[1] = 0.0f;
    }
}

// ---------------- per-sample depthwise 9-tap (edge pad) + mean accumulate ----------------
#define DTL 1024
__global__ __launch_bounds__(256) void dw_kernel(
    const float* __restrict__ x, const float* __restrict__ lo, const float* __restrict__ hi,
    float* __restrict__ out_a, float* __restrict__ out_d, float* __restrict__ feat_next)
{
    int row = blockIdx.y;
    int b   = row >> 7;
    int l0  = blockIdx.x * DTL;
    __shared__ __align__(16) float s[DTL + 16];
    __shared__ float wsum[8];
    const float* xr = x + (size_t)row * L;
    int t = threadIdx.x, lane = t & 31, wid = t >> 5;
    {
        const float4* xv = (const float4*)(xr + l0);
        ((float4*)(s + 4))[t] = xv[t];
    }
    if (t < 4){
        int li = l0 - 4 + t;
        s[t] = xr[max(li, 0)];
        int ri = l0 + DTL + t;
        s[DTL + 4 + t] = xr[min(ri, L-1)];
    }
    unsigned long long pf[FL];
    #pragma unroll
    for (int k = 0; k < FL; k++) pf[k] = pack2(__ldg(&lo[b*FL+k]), __ldg(&hi[b*FL+k]));
    __syncthreads();

    int i0 = t * 4;
    float win[12];
    #pragma unroll
    for (int j = 0; j < 12; j++) win[j] = s[i0 + j];
    unsigned long long acc[4];
    #pragma unroll
    for (int p = 0; p < 4; p++) acc[p] = 0ull;
    #pragma unroll
    for (int k = 0; k < FL; k++){
        #pragma unroll
        for (int p = 0; p < 4; p++){
            unsigned long long vv = pack2(win[p+k], win[p+k]);
            acc[p] = fma2(vv, pf[k], acc[p]);
        }
    }
    float4 ra, rd;
    float2 f0 = unpack2(acc[0]), f1 = unpack2(acc[1]), f2 = unpack2(acc[2]), f3 = unpack2(acc[3]);
    ra.x = f0.x; ra.y = f1.x; ra.z = f2.x; ra.w = f3.x;
    rd.x = f0.y; rd.y = f1.y; rd.z = f2.y; rd.w = f3.y;
    size_t idx = (size_t)row*L + l0 + i0;
    *(float4*)(out_a + idx) = ra;
    *(float4*)(out_d + idx) = rd;

    // accumulate row mean of out_a for the next level
    if (feat_next){
        float s4 = (ra.x + ra.y) + (ra.z + ra.w);
        #pragma unroll
        for (int off = 16; off > 0; off >>= 1) s4 += __shfl_xor_sync(0xffffffffu, s4, off);
        if (lane == 0) wsum[wid] = s4;
        __syncthreads();
        if (t == 0){
            float tot = 0.f;
            #pragma unroll
            for (int w = 0; w < 8; w++) tot += wsum[w];
            atomicAdd(feat_next + row, tot * (1.0f/(float)L));
        }
    }
}

// ---------------- weight prep ----------------
__global__ void transpose_w_kernel(const float* __restrict__ gw, float* __restrict__ wt){
    int idx = blockIdx.x*256 + threadIdx.x;
    if (idx < 3*C*C*3){
        int lvl = idx / (C*C*3);
        int r   = idx % (C*C*3);
        int ci  = r / (3*C);
        int k   = (r % (3*C)) / C;
        int co  = r % C;
        wt[idx] = gw[(size_t)lvl*C*C*3 + ((size_t)co*C + ci)*3 + k];
    }
}
__global__ void prep2_kernel(const float* __restrict__ attn2_w, float* __restrict__ w2t,
                             float* __restrict__ feat){
    int idx = blockIdx.x*256 + threadIdx.x;
    if (idx < 2*32*C){
        int lvl = idx / (32*C);
        int r   = idx % (32*C);
        int ci  = r >> 7, co = r & 127;
        w2t[idx] = attn2_w[((size_t)lvl*C + co)*32 + ci];
    }
    if (idx < 2*B*C) feat[B*C + idx] = 0.f;   // zero feat levels 1,2
}

// ---------------- fused gates (+ optional attn2) ----------------
// conv gate: z1 = conv3(cur)+bias; attn: z2 = W2*a + bias2
// det' = det*(1+sigmoid(z2)) [ATTN], yh = det' [ATTN], out = cur + sigmoid(z1)*det'
#define SO_X  0
#define SO_W  (C*66*4)                 // 33792
#define SO_A  (SO_W + 8*3*C*4)         // 46080
#define SO_W2 (SO_A + 32*64*4)         // 54272
#define GSM_TOTAL (SO_W2 + 32*C*4)     // 70656

template<bool ATTN>
__global__ __launch_bounds__(256) void gatesf_kernel(
    const float* __restrict__ cur, const float* __restrict__ det_raw,
    const float* __restrict__ wt, const float* __restrict__ bias,
    const float* __restrict__ a, const float* __restrict__ w2t, const float* __restrict__ bias2,
    float* __restrict__ yh_out, float* __restrict__ out)
{
    extern __shared__ __align__(16) char smem[];
    float* s_x  = (float*)(smem + SO_X);     // [ci][66]
    float* s_w  = (float*)(smem + SO_W);     // [8*3][128]
    float* s_a  = (float*)(smem + SO_A);     // [32][64]
    float* s_w2 = (float*)(smem + SO_W2);    // [32][128]
    int l0 = blockIdx.x*64, b = blockIdx.y, t = threadIdx.x;
    for (int idx = t; idx < C*66; idx += 256){
        int ci = idx/66, j = idx%66;
        int li = l0 + j - 1;
        float v = 0.f;
        if (li >= 0 && li < L) v = cur[((size_t)(b*C+ci))*L + li];
        s_x[idx] = v;
    }
    if (ATTN){
        for (int idx = t; idx < 32*64; idx += 256){
            int ci = idx >> 6, j = idx & 63;
            s_a[idx] = a[((size_t)(b*32+ci))*L + l0 + j];
        }
        for (int idx = t; idx < 32*C; idx += 256) s_w2[idx] = w2t[idx];
    }
    int wid = t >> 5, lane = t & 31, co0 = wid*16;
    unsigned long long acc[8][2];
    #pragma unroll
    for (int c = 0; c < 8; c++){ acc[c][0] = 0ull; acc[c][1] = 0ull; }

    for (int ci0 = 0; ci0 < C; ci0 += 8){
        __syncthreads();
        for (int idx = t; idx < 8*3*C; idx += 256) s_w[idx] = wt[ci0*3*C + idx];
        __syncthreads();
        #pragma unroll
        for (int ci = 0; ci < 8; ci++){
            #pragma unroll
            for (int k = 0; k < 3; k++){
                const ulonglong2* wp = (const ulonglong2*)(&s_w[(ci*3+k)*C + co0]);
                unsigned long long wr[8];
                ((ulonglong2*)wr)[0] = wp[0];
                ((ulonglong2*)wr)[1] = wp[1];
                ((ulonglong2*)wr)[2] = wp[2];
                ((ulonglong2*)wr)[3] = wp[3];
                float x0 = s_x[(ci0+ci)*66 + lane + k];
                float x1 = s_x[(ci0+ci)*66 + lane + 32 + k];
                unsigned long long p0 = pack2(x0, x0);
                unsigned long long p1 = pack2(x1, x1);
                #pragma unroll
                for (int c = 0; c < 8; c++){
                    acc[c][0] = fma2(wr[c], p0, acc[c][0]);
                    acc[c][1] = fma2(wr[c], p1, acc[c][1]);
                }
            }
        }
    }

    unsigned long long acc2[8][2];
    if (ATTN){
        #pragma unroll
        for (int c = 0; c < 8; c++){ acc2[c][0] = 0ull; acc2[c][1] = 0ull; }
        #pragma unroll 4
        for (int ci = 0; ci < 32; ci++){
            const ulonglong2* wp = (const ulonglong2*)(&s_w2[ci*C + co0]);
            unsigned long long wr[8];
            ((ulonglong2*)wr)[0] = wp[0];
            ((ulonglong2*)wr)[1] = wp[1];
            ((ulonglong2*)wr)[2] = wp[2];
            ((ulonglong2*)wr)[3] = wp[3];
            float x0 = s_a[ci*64 + lane];
            float x1 = s_a[ci*64 + lane + 32];
            unsigned long long p0 = pack2(x0, x0);
            unsigned long long p1 = pack2(x1, x1);
            #pragma unroll
            for (int c = 0; c < 8; c++){
                acc2[c][0] = fma2(wr[c], p0, acc2[c][0]);
                acc2[c][1] = fma2(wr[c], p1, acc2[c][1]);
            }
        }
    }

    #pragma unroll
    for (int c = 0; c < 8; c++){
        int co = co0 + 2*c;
        float b0 = bias[co], b1 = bias[co+1];
        float b20 = 0.f, b21 = 0.f;
        if (ATTN){ b20 = bias2[co]; b21 = bias2[co+1]; }
        #pragma unroll
        for (int j = 0; j < 2; j++){
            float2 f = unpack2(acc[c][j]);
            size_t idx0 = ((size_t)(b*C+co))*L + l0 + lane + j*32;
            size_t idx1 = idx0 + L;
            float d0 = det_raw[idx0];
            float d1 = det_raw[idx1];
            if (ATTN){
                float2 f2 = unpack2(acc2[c][j]);
                d0 *= 1.0f + sigmoid_f(f2.x + b20);
                d1 *= 1.0f + sigmoid_f(f2.y + b21);
                yh_out[idx0] = d0;
                yh_out[idx1] = d1;
            }
            float c0 = s_x[co*66     + lane + j*32 + 1];
            float c1 = s_x[(co+1)*66 + lane + j*32 + 1];
            out[idx0] = c0 + sigmoid_f(f.x + b0)*d0;
            out[idx1] = c1 + sigmoid_f(f.y + b1)*d1;
        }
    }
}

// ---------------- attn1: 1x1 conv 128->32 + gelu (FFMA2) ----------------
__global__ __launch_bounds__(256) void attn1_kernel(
    const float* __restrict__ cur, const float* __restrict__ w,
    const float* __restrict__ bias, float* __restrict__ outa)
{
    __shared__ __align__(16) float s_x[32*128];
    __shared__ __align__(16) float s_w[128*32];
    int b = blockIdx.y, l0 = blockIdx.x*128, t = threadIdx.x;
    for (int idx = t; idx < C*32; idx += 256){
        int ci = idx >> 5, co = idx & 31;
        s_w[idx] = w[co*C + ci];
    }
    int wid = t >> 5, lane = t & 31, co0 = wid*4;
    unsigned long long acc[2][4];
    #pragma unroll
    for (int c = 0; c < 2; c++)
        #pragma unroll
        for (int j = 0; j < 4; j++) acc[c][j] = 0ull;

    for (int ci0 = 0; ci0 < C; ci0 += 32){
        __syncthreads();
        for (int idx = t; idx < 32*128; idx += 256){
            int ci = idx >> 7, l = idx & 127;
            s_x[idx] = cur[((size_t)(b*C + ci0 + ci))*L + l0 + l];
        }
        __syncthreads();
        #pragma unroll 4
        for (int ci = 0; ci < 32; ci++){
            unsigned long long wr[2];
            wr[0] = *(const unsigned long long*)(&s_w[(ci0+ci)*32 + co0]);
            wr[1] = *(const unsigned long long*)(&s_w[(ci0+ci)*32 + co0 + 2]);
            #pragma unroll
            for (int j = 0; j < 4; j++){
                float xv = s_x[ci*128 + lane + j*32];
                unsigned long long p = pack2(xv, xv);
                acc[0][j] = fma2(wr[0], p, acc[0][j]);
                acc[1][j] = fma2(wr[1], p, acc[1][j]);
            }
        }
    }
    #pragma unroll
    for (int c = 0; c < 2; c++){
        int co = co0 + 2*c;
        float b0 = bias[co], b1 = bias[co+1];
        #pragma unroll
        for (int j = 0; j < 4; j++){
            float2 f = unpack2(acc[c][j]);
            size_t idx0 = ((size_t)(b*32 + co))*L + l0 + lane + j*32;
            outa[idx0]     = gelu_f(f.x + b0);
            outa[idx0 + L] = gelu_f(f.y + b1);
        }
    }
}

// ---------------- host launch ----------------
extern "C" void kernel_launch(void* const* d_in, const int* in_sizes, int n_in,
                              void* d_out, int out_size)
{
    const float* x       = (const float*)d_in[0];
    const float* stat_w  = (const float*)d_in[1];
    const float* stat_b  = (const float*)d_in[2];
    const float* wg1_w   = (const float*)d_in[3];
    const float* wg1_b   = (const float*)d_in[4];
    const float* wg2_w   = (const float*)d_in[5];
    const float* wg2_b   = (const float*)d_in[6];
    const float* gates_w = (const float*)d_in[7];
    const float* gates_b = (const float*)d_in[8];
    const float* attn1_w = (const float*)d_in[9];
    const float* attn1_b = (const float*)d_in[10];
    const float* attn2_w = (const float*)d_in[11];
    const float* attn2_b = (const float*)d_in[12];
    float* out = (float*)d_out;

    float *a1, *a2, *a3, *attn, *feat, *wt, *w2t;
    cudaGetSymbolAddress((void**)&a1,   g_a1);
    cudaGetSymbolAddress((void**)&a2,   g_a2);
    cudaGetSymbolAddress((void**)&a3,   g_a3);
    cudaGetSymbolAddress((void**)&attn, g_attn);
    cudaGetSymbolAddress((void**)&feat, g_feat);
    cudaGetSymbolAddress((void**)&wt,   g_wt);
    cudaGetSymbolAddress((void**)&w2t,  g_w2t);

    float* yl  = out;
    float* yh0 = out + NYL;
    float* yh1 = out + 2*NYL;
    float* yh2 = out + 3*NYL;
    float* scal= out + 4*NYL;
    float* lo_all = out + 4*NYL + 2;
    float* hi_all = lo_all + 3*B*FL;

    cudaFuncSetAttribute(gatesf_kernel<true>,  cudaFuncAttributeMaxDynamicSharedMemorySize, GSM_TOTAL);
    cudaFuncSetAttribute(gatesf_kernel<false>, cudaFuncAttributeMaxDynamicSharedMemorySize, GSM_TOTAL);

    transpose_w_kernel<<<(3*C*C*3 + 255)/256, 256>>>(gates_w, wt);
    prep2_kernel<<<(2*32*C + 255)/256, 256>>>(attn2_w, w2t, feat);

    const float* ain[3]  = {x, a1, a2};
    float*       aout[3] = {a1, a2, a3};
    float*       dets[3] = {yh0, yh1, yh2};

    mean_kernel<<<NROW, 256>>>(x, feat);
    for (int lvl = 0; lvl < 3; lvl++){
        float* lo = lo_all + lvl*B*FL;
        float* hi = hi_all + lvl*B*FL;
        mlp_kernel<<<B, 512>>>(feat + lvl*B*C, stat_w, stat_b, wg1_w, wg1_b, wg2_w, wg2_b, lo, hi);
        float* fnext = (lvl < 2) ? (feat + (lvl+1)*B*C) : nullptr;
        dw_kernel<<<dim3(L/DTL, NROW), 256>>>(ain[lvl], lo, hi, aout[lvl], dets[lvl], fnext);
    }

    ortho_kernel<<<1, 32>>>(lo_all + 2*B*FL, scal);

    // reconstruction: i = 2 (no attn) — cur=a3, det=yh2 (raw), out -> a1 (reused)
    gatesf_kernel<false><<<dim3(L/64, B), 256, GSM_TOTAL>>>(
        a3, yh2, wt + 2*C*3*C, gates_b + 2*C, nullptr, nullptr, nullptr, nullptr, a1);
    // i = 1
    attn1_kernel<<<dim3(L/128, B), 256>>>(a1, attn1_w + 1*(C/4)*C, attn1_b + (C/4), attn);
    gatesf_kernel<true><<<dim3(L/64, B), 256, GSM_TOTAL>>>(
        a1, yh1, wt + 1*C*3*C, gates_b + 1*C, attn, w2t + 32*C, attn2_b + C, yh1, a2);
    // i = 0
    attn1_kernel<<<dim3(L/128, B), 256>>>(a2, attn1_w, attn1_b, attn);
    gatesf_kernel<true><<<dim3(L/64, B), 256, GSM_TOTAL>>>(
        a2, yh0, wt, gates_b, attn, w2t, attn2_b, yh0, yl);
}

// round 8
// speedup vs baseline: 1.2623x; 1.1720x over previous
#include <cuda_runtime.h>
#include <math.h>
#include <stdint.h>

#define B 32
#define C 128
#define L 4096
#define NROW (B*C)
#define BCL (B*C*L)            // 16777216
#define FL 9
#define DIM 512
#define NYL ((size_t)BCL)

// ---------------- scratch (device globals; no allocation) ----------------
__device__ float g_a1[BCL];
__device__ float g_a2[BCL];
__device__ float g_a3[BCL];
__device__ float g_attn[B*(C/4)*L];
__device__ float g_feat[3*B*C];          // per-level feature means
__device__ float g_h1[B*DIM];
__device__ float g_h2[B*2*DIM];
__device__ float g_wt[3*C*3*C];          // gates weights [lvl][ci][k][co]
__device__ float g_w2t[2*32*C];          // attn2 weights [lvl][ci][co]

__device__ __forceinline__ float gelu_f(float x){
    return 0.5f*x*(1.0f+erff(x*0.7071067811865476f));
}
__device__ __forceinline__ float sigmoid_f(float x){
    return 1.0f/(1.0f+expf(-x));
}

// ---- packed f32x2 helpers (Blackwell FFMA2) ----
__device__ __forceinline__ unsigned long long pack2(float lo, float hi){
    unsigned long long r;
    asm("mov.b64 %0, {%1, %2};" : "=l"(r) : "f"(lo), "f"(hi));
    return r;
}
__device__ __forceinline__ unsigned long long fma2(unsigned long long a, unsigned long long b, unsigned long long c){
    unsigned long long d;
    asm("fma.rn.f32x2 %0, %1, %2, %3;" : "=l"(d) : "l"(a), "l"(b), "l"(c));
    return d;
}
__device__ __forceinline__ float2 unpack2(unsigned long long v){
    float2 f;
    asm("mov.b64 {%0, %1}, %2;" : "=f"(f.x), "=f"(f.y) : "l"(v));
    return f;
}

// ---------------- mean over L (level 0 only) ----------------
__global__ __launch_bounds__(256) void mean_kernel(const float* __restrict__ x,
                                                   float* __restrict__ feat){
    int row = blockIdx.x;
    const float4* p = (const float4*)(x + (size_t)row*L);
    float s = 0.f;
    for (int i = threadIdx.x; i < L/4; i += 256){
        float4 v = p[i];
        s += (v.x+v.y)+(v.z+v.w);
    }
    __shared__ float red[256];
    red[threadIdx.x] = s; __syncthreads();
    for (int off = 128; off > 0; off >>= 1){
        if (threadIdx.x < off) red[threadIdx.x] += red[threadIdx.x+off];
        __syncthreads();
    }
    if (threadIdx.x == 0) feat[row] = red[0] * (1.0f/(float)L);
}

// ---------------- MLP layer 1: feat[32,128] -> h1[32,512], warp per output ----------------
__global__ __launch_bounds__(256) void mlp_l1(const float* __restrict__ feat,
                                              const float* __restrict__ sw, const float* __restrict__ sb,
                                              float* __restrict__ h1){
    int b = blockIdx.y;
    int j = blockIdx.x*8 + (threadIdx.x >> 5);
    int lane = threadIdx.x & 31;
    float4 w = ((const float4*)(sw + (size_t)j*C))[lane];
    float4 f = ((const float4*)(feat + b*C))[lane];
    float s = w.x*f.x + w.y*f.y + w.z*f.z + w.w*f.w;
    #pragma unroll
    for (int off = 16; off > 0; off >>= 1) s += __shfl_xor_sync(0xffffffffu, s, off);
    if (lane == 0) h1[b*DIM + j] = gelu_f(s + sb[j]);
}

// ---------------- MLP layer 2: h1[32,512] -> h2[32,1024], warp per output ----------------
__global__ __launch_bounds__(256) void mlp_l2(const float* __restrict__ h1,
                                              const float* __restrict__ w1, const float* __restrict__ b1,
                                              float* __restrict__ h2){
    __shared__ __align__(16) float sh[DIM];
    int b = blockIdx.y, t = threadIdx.x;
    for (int i = t; i < DIM/4; i += 256)
        ((float4*)sh)[i] = ((const float4*)(h1 + b*DIM))[i];
    __syncthreads();
    int j = blockIdx.x*8 + (t >> 5);
    int lane = t & 31;
    const float4* wr = (const float4*)(w1 + (size_t)j*DIM);
    float s = 0.f;
    #pragma unroll
    for (int i = 0; i < 4; i++){
        float4 w = wr[i*32 + lane];
        float4 f = ((const float4*)sh)[i*32 + lane];
        s += w.x*f.x + w.y*f.y + w.z*f.z + w.w*f.w;
    }
    #pragma unroll
    for (int off = 16; off > 0; off >>= 1) s += __shfl_xor_sync(0xffffffffu, s, off);
    if (lane == 0) h2[b*2*DIM + j] = gelu_f(s + b1[j]);
}

// ---------------- MLP layer 3: h2[32,1024] -> lo/hi[32,9], warp per output ----------------
__global__ __launch_bounds__(576) void mlp_l3(const float* __restrict__ h2,
                                              const float* __restrict__ w2, const float* __restrict__ b2,
                                              float* __restrict__ lo, float* __restrict__ hi){
    __shared__ __align__(16) float sh[2*DIM];
    int b = blockIdx.x, t = threadIdx.x;
    for (int i = t; i < 2*DIM/4; i += 576)
        ((float4*)sh)[i] = ((const float4*)(h2 + b*2*DIM))[i];
    __syncthreads();
    int j = t >> 5, lane = t & 31;     // 18 warps
    const float4* wr = (const float4*)(w2 + (size_t)j*2*DIM);
    float s = 0.f;
    #pragma unroll
    for (int i = 0; i < 8; i++){
        float4 w = wr[i*32 + lane];
        float4 f = ((const float4*)sh)[i*32 + lane];
        s += w.x*f.x + w.y*f.y + w.z*f.z + w.w*f.w;
    }
    #pragma unroll
    for (int off = 16; off > 0; off >>= 1) s += __shfl_xor_sync(0xffffffffu, s, off);
    if (lane == 0){
        float v = s + b2[j];
        if (j < FL) lo[b*FL + j] = v;
        else        hi[b*FL + (j-FL)] = v;
    }
}

// ---------------- ortho loss (last level only) + energy=0 ----------------
__global__ void ortho_kernel(const float* __restrict__ lo, float* __restrict__ out_scalars){
    int b = threadIdx.x;
    float v[FL]; float ss = 0.f;
    #pragma unroll
    for (int k = 0; k < FL; k++){ v[k] = lo[b*FL+k]; ss += v[k]*v[k]; }
    float den = sqrtf(ss) + 1e-8f;
    float S = 0.f, sq = 0.f;
    #pragma unroll
    for (int k = 0; k < FL; k++){
        float n = v[k]/den;
        S  += fabsf(n);
        sq += n*n;
    }
    float S2  = S*S;
    float amp = fabsf(sq - 1.0f);
    float sm  = fabsf(v[0]);
    #pragma unroll
    for (int k = 1; k < FL; k++) sm += fabsf(v[k]-v[k-1]);
    sm += fabsf(v[FL-1]);
    #pragma unroll
    for (int off = 16; off > 0; off >>= 1){
        S2  += __shfl_xor_sync(0xffffffffu, S2,  off);
        amp += __shfl_xor_sync(0xffffffffu, amp, off);
        sm  += __shfl_xor_sync(0xffffffffu, sm,  off);
    }
    if (b == 0){
        float shift  = 3.0f * S2 / (32.0f*81.0f);
        float ampm   = amp / 32.0f;
        float smm    = sm / (32.0f*10.0f);
        out_scalars[0] = 0.01f*(shift + ampm) + 0.1f*smm;
        out_scalars[1] = 0.0f;
    }
}

// ---------------- per-sample depthwise 9-tap (edge pad) + mean accumulate ----------------
#define DTL 1024
__global__ __launch_bounds__(256) void dw_kernel(
    const float* __restrict__ x, const float* __restrict__ lo, const float* __restrict__ hi,
    float* __restrict__ out_a, float* __restrict__ out_d, float* __restrict__ feat_next)
{
    int row = blockIdx.y;
    int b   = row >> 7;
    int l0  = blockIdx.x * DTL;
    __shared__ __align__(16) float s[DTL + 16];
    __shared__ float wsum[8];
    const float* xr = x + (size_t)row * L;
    int t = threadIdx.x, lane = t & 31, wid = t >> 5;
    {
        const float4* xv = (const float4*)(xr + l0);
        ((float4*)(s + 4))[t] = xv[t];
    }
    if (t < 4){
        int li = l0 - 4 + t;
        s[t] = xr[max(li, 0)];
        int ri = l0 + DTL + t;
        s[DTL + 4 + t] = xr[min(ri, L-1)];
    }
    unsigned long long pf[FL];
    #pragma unroll
    for (int k = 0; k < FL; k++) pf[k] = pack2(__ldg(&lo[b*FL+k]), __ldg(&hi[b*FL+k]));
    __syncthreads();

    int i0 = t * 4;
    float win[12];
    #pragma unroll
    for (int j = 0; j < 12; j++) win[j] = s[i0 + j];
    unsigned long long acc[4];
    #pragma unroll
    for (int p = 0; p < 4; p++) acc[p] = 0ull;
    #pragma unroll
    for (int k = 0; k < FL; k++){
        #pragma unroll
        for (int p = 0; p < 4; p++){
            unsigned long long vv = pack2(win[p+k], win[p+k]);
            acc[p] = fma2(vv, pf[k], acc[p]);
        }
    }
    float4 ra, rd;
    float2 f0 = unpack2(acc[0]), f1 = unpack2(acc[1]), f2 = unpack2(acc[2]), f3 = unpack2(acc[3]);
    ra.x = f0.x; ra.y = f1.x; ra.z = f2.x; ra.w = f3.x;
    rd.x = f0.y; rd.y = f1.y; rd.z = f2.y; rd.w = f3.y;
    size_t idx = (size_t)row*L + l0 + i0;
    *(float4*)(out_a + idx) = ra;
    *(float4*)(out_d + idx) = rd;

    if (feat_next){
        float s4 = (ra.x + ra.y) + (ra.z + ra.w);
        #pragma unroll
        for (int off = 16; off > 0; off >>= 1) s4 += __shfl_xor_sync(0xffffffffu, s4, off);
        if (lane == 0) wsum[wid] = s4;
        __syncthreads();
        if (t == 0){
            float tot = 0.f;
            #pragma unroll
            for (int w = 0; w < 8; w++) tot += wsum[w];
            atomicAdd(feat_next + row, tot * (1.0f/(float)L));
        }
    }
}

// ---------------- weight prep ----------------
__global__ void transpose_w_kernel(const float* __restrict__ gw, float* __restrict__ wt){
    int idx = blockIdx.x*256 + threadIdx.x;
    if (idx < 3*C*C*3){
        int lvl = idx / (C*C*3);
        int r   = idx % (C*C*3);
        int ci  = r / (3*C);
        int k   = (r % (3*C)) / C;
        int co  = r % C;
        wt[idx] = gw[(size_t)lvl*C*C*3 + ((size_t)co*C + ci)*3 + k];
    }
}
__global__ void prep2_kernel(const float* __restrict__ attn2_w, float* __restrict__ w2t,
                             float* __restrict__ feat){
    int idx = blockIdx.x*256 + threadIdx.x;
    if (idx < 2*32*C){
        int lvl = idx / (32*C);
        int r   = idx % (32*C);
        int ci  = r >> 7, co = r & 127;
        w2t[idx] = attn2_w[((size_t)lvl*C + co)*32 + ci];
    }
    if (idx < 2*B*C) feat[B*C + idx] = 0.f;   // zero feat levels 1,2
}

// ---------------- fused gates (+ optional attn2) ----------------
#define SO_X  0
#define SO_W  (C*66*4)                 // 33792
#define SO_A  (SO_W + 8*3*C*4)         // 46080
#define SO_W2 (SO_A + 32*64*4)         // 54272
#define GSM_ATTN (SO_W2 + 32*C*4)      // 70656
#define GSM_PLAIN SO_A                 // 46080 (no s_a/s_w2)

template<bool ATTN>
__global__ __launch_bounds__(256) void gatesf_kernel(
    const float* __restrict__ cur, const float* __restrict__ det_raw,
    const float* __restrict__ wt, const float* __restrict__ bias,
    const float* __restrict__ a, const float* __restrict__ w2t, const float* __restrict__ bias2,
    float* __restrict__ yh_out, float* __restrict__ out)
{
    extern __shared__ __align__(16) char smem[];
    float* s_x  = (float*)(smem + SO_X);     // [ci][66]
    float* s_w  = (float*)(smem + SO_W);     // [8*3][128]
    float* s_a  = (float*)(smem + SO_A);     // [32][64]
    float* s_w2 = (float*)(smem + SO_W2);    // [32][128]
    int l0 = blockIdx.x*64, b = blockIdx.y, t = threadIdx.x;
    for (int idx = t; idx < C*66; idx += 256){
        int ci = idx/66, j = idx%66;
        int li = l0 + j - 1;
        float v = 0.f;
        if (li >= 0 && li < L) v = cur[((size_t)(b*C+ci))*L + li];
        s_x[idx] = v;
    }
    if (ATTN){
        for (int idx = t; idx < 32*64; idx += 256){
            int ci = idx >> 6, j = idx & 63;
            s_a[idx] = a[((size_t)(b*32+ci))*L + l0 + j];
        }
        for (int idx = t; idx < 32*C; idx += 256) s_w2[idx] = w2t[idx];
    }
    int wid = t >> 5, lane = t & 31, co0 = wid*16;
    unsigned long long acc[8][2];
    #pragma unroll
    for (int c = 0; c < 8; c++){ acc[c][0] = 0ull; acc[c][1] = 0ull; }

    for (int ci0 = 0; ci0 < C; ci0 += 8){
        __syncthreads();
        for (int idx = t; idx < 8*3*C; idx += 256) s_w[idx] = wt[ci0*3*C + idx];
        __syncthreads();
        #pragma unroll
        for (int ci = 0; ci < 8; ci++){
            #pragma unroll
            for (int k = 0; k < 3; k++){
                const ulonglong2* wp = (const ulonglong2*)(&s_w[(ci*3+k)*C + co0]);
                unsigned long long wr[8];
                ((ulonglong2*)wr)[0] = wp[0];
                ((ulonglong2*)wr)[1] = wp[1];
                ((ulonglong2*)wr)[2] = wp[2];
                ((ulonglong2*)wr)[3] = wp[3];
                float x0 = s_x[(ci0+ci)*66 + lane + k];
                float x1 = s_x[(ci0+ci)*66 + lane + 32 + k];
                unsigned long long p0 = pack2(x0, x0);
                unsigned long long p1 = pack2(x1, x1);
                #pragma unroll
                for (int c = 0; c < 8; c++){
                    acc[c][0] = fma2(wr[c], p0, acc[c][0]);
                    acc[c][1] = fma2(wr[c], p1, acc[c][1]);
                }
            }
        }
    }

    unsigned long long acc2[8][2];
    if (ATTN){
        #pragma unroll
        for (int c = 0; c < 8; c++){ acc2[c][0] = 0ull; acc2[c][1] = 0ull; }
        #pragma unroll 4
        for (int ci = 0; ci < 32; ci++){
            const ulonglong2* wp = (const ulonglong2*)(&s_w2[ci*C + co0]);
            unsigned long long wr[8];
            ((ulonglong2*)wr)[0] = wp[0];
            ((ulonglong2*)wr)[1] = wp[1];
            ((ulonglong2*)wr)[2] = wp[2];
            ((ulonglong2*)wr)[3] = wp[3];
            float x0 = s_a[ci*64 + lane];
            float x1 = s_a[ci*64 + lane + 32];
            unsigned long long p0 = pack2(x0, x0);
            unsigned long long p1 = pack2(x1, x1);
            #pragma unroll
            for (int c = 0; c < 8; c++){
                acc2[c][0] = fma2(wr[c], p0, acc2[c][0]);
                acc2[c][1] = fma2(wr[c], p1, acc2[c][1]);
            }
        }
    }

    #pragma unroll
    for (int c = 0; c < 8; c++){
        int co = co0 + 2*c;
        float b0 = bias[co], b1 = bias[co+1];
        float b20 = 0.f, b21 = 0.f;
        if (ATTN){ b20 = bias2[co]; b21 = bias2[co+1]; }
        #pragma unroll
        for (int j = 0; j < 2; j++){
            float2 f = unpack2(acc[c][j]);
            size_t idx0 = ((size_t)(b*C+co))*L + l0 + lane + j*32;
            size_t idx1 = idx0 + L;
            float d0 = det_raw[idx0];
            float d1 = det_raw[idx1];
            if (ATTN){
                float2 f2 = unpack2(acc2[c][j]);
                d0 *= 1.0f + sigmoid_f(f2.x + b20);
                d1 *= 1.0f + sigmoid_f(f2.y + b21);
                yh_out[idx0] = d0;
                yh_out[idx1] = d1;
            }
            float c0 = s_x[co*66     + lane + j*32 + 1];
            float c1 = s_x[(co+1)*66 + lane + j*32 + 1];
            out[idx0] = c0 + sigmoid_f(f.x + b0)*d0;
            out[idx1] = c1 + sigmoid_f(f.y + b1)*d1;
        }
    }
}

// ---------------- attn1: 1x1 conv 128->32 + gelu (FFMA2) ----------------
__global__ __launch_bounds__(256) void attn1_kernel(
    const float* __restrict__ cur, const float* __restrict__ w,
    const float* __restrict__ bias, float* __restrict__ outa)
{
    __shared__ __align__(16) float s_x[32*128];
    __shared__ __align__(16) float s_w[128*32];
    int b = blockIdx.y, l0 = blockIdx.x*128, t = threadIdx.x;
    for (int idx = t; idx < C*32; idx += 256){
        int ci = idx >> 5, co = idx & 31;
        s_w[idx] = w[co*C + ci];
    }
    int wid = t >> 5, lane = t & 31, co0 = wid*4;
    unsigned long long acc[2][4];
    #pragma unroll
    for (int c = 0; c < 2; c++)
        #pragma unroll
        for (int j = 0; j < 4; j++) acc[c][j] = 0ull;

    for (int ci0 = 0; ci0 < C; ci0 += 32){
        __syncthreads();
        for (int idx = t; idx < 32*128; idx += 256){
            int ci = idx >> 7, l = idx & 127;
            s_x[idx] = cur[((size_t)(b*C + ci0 + ci))*L + l0 + l];
        }
        __syncthreads();
        #pragma unroll 4
        for (int ci = 0; ci < 32; ci++){
            unsigned long long wr[2];
            wr[0] = *(const unsigned long long*)(&s_w[(ci0+ci)*32 + co0]);
            wr[1] = *(const unsigned long long*)(&s_w[(ci0+ci)*32 + co0 + 2]);
            #pragma unroll
            for (int j = 0; j < 4; j++){
                float xv = s_x[ci*128 + lane + j*32];
                unsigned long long p = pack2(xv, xv);
                acc[0][j] = fma2(wr[0], p, acc[0][j]);
                acc[1][j] = fma2(wr[1], p, acc[1][j]);
            }
        }
    }
    #pragma unroll
    for (int c = 0; c < 2; c++){
        int co = co0 + 2*c;
        float b0 = bias[co], b1 = bias[co+1];
        #pragma unroll
        for (int j = 0; j < 4; j++){
            float2 f = unpack2(acc[c][j]);
            size_t idx0 = ((size_t)(b*32 + co))*L + l0 + lane + j*32;
            outa[idx0]     = gelu_f(f.x + b0);
            outa[idx0 + L] = gelu_f(f.y + b1);
        }
    }
}

// ---------------- host launch ----------------
extern "C" void kernel_launch(void* const* d_in, const int* in_sizes, int n_in,
                              void* d_out, int out_size)
{
    const float* x       = (const float*)d_in[0];
    const float* stat_w  = (const float*)d_in[1];
    const float* stat_b  = (const float*)d_in[2];
    const float* wg1_w   = (const float*)d_in[3];
    const float* wg1_b   = (const float*)d_in[4];
    const float* wg2_w   = (const float*)d_in[5];
    const float* wg2_b   = (const float*)d_in[6];
    const float* gates_w = (const float*)d_in[7];
    const float* gates_b = (const float*)d_in[8];
    const float* attn1_w = (const float*)d_in[9];
    const float* attn1_b = (const float*)d_in[10];
    const float* attn2_w = (const float*)d_in[11];
    const float* attn2_b = (const float*)d_in[12];
    float* out = (float*)d_out;

    float *a1, *a2, *a3, *attn, *feat, *h1, *h2, *wt, *w2t;
    cudaGetSymbolAddress((void**)&a1,   g_a1);
    cudaGetSymbolAddress((void**)&a2,   g_a2);
    cudaGetSymbolAddress((void**)&a3,   g_a3);
    cudaGetSymbolAddress((void**)&attn, g_attn);
    cudaGetSymbolAddress((void**)&feat, g_feat);
    cudaGetSymbolAddress((void**)&h1,   g_h1);
    cudaGetSymbolAddress((void**)&h2,   g_h2);
    cudaGetSymbolAddress((void**)&wt,   g_wt);
    cudaGetSymbolAddress((void**)&w2t,  g_w2t);

    float* yl  = out;
    float* yh0 = out + NYL;
    float* yh1 = out + 2*NYL;
    float* yh2 = out + 3*NYL;
    float* scal= out + 4*NYL;
    float* lo_all = out + 4*NYL + 2;
    float* hi_all = lo_all + 3*B*FL;

    cudaFuncSetAttribute(gatesf_kernel<true>,  cudaFuncAttributeMaxDynamicSharedMemorySize, GSM_ATTN);
    cudaFuncSetAttribute(gatesf_kernel<false>, cudaFuncAttributeMaxDynamicSharedMemorySize, GSM_PLAIN);

    transpose_w_kernel<<<(3*C*C*3 + 255)/256, 256>>>(gates_w, wt);
    prep2_kernel<<<(2*32*C + 255)/256, 256>>>(attn2_w, w2t, feat);

    const float* ain[3]  = {x, a1, a2};
    float*       aout[3] = {a1, a2, a3};
    float*       dets[3] = {yh0, yh1, yh2};

    mean_kernel<<<NROW, 256>>>(x, feat);
    for (int lvl = 0; lvl < 3; lvl++){
        float* lo = lo_all + lvl*B*FL;
        float* hi = hi_all + lvl*B*FL;
        const float* f = feat + lvl*B*C;
        mlp_l1<<<dim3(DIM/8, B), 256>>>(f, stat_w, stat_b, h1);
        mlp_l2<<<dim3(2*DIM/8, B), 256>>>(h1, wg1_w, wg1_b, h2);
        mlp_l3<<<B, 576>>>(h2, wg2_w, wg2_b, lo, hi);
        float* fnext = (lvl < 2) ? (feat + (lvl+1)*B*C) : nullptr;
        dw_kernel<<<dim3(L/DTL, NROW), 256>>>(ain[lvl], lo, hi, aout[lvl], dets[lvl], fnext);
    }

    ortho_kernel<<<1, 32>>>(lo_all + 2*B*FL, scal);

    // reconstruction: i = 2 (no attn)
    gatesf_kernel<false><<<dim3(L/64, B), 256, GSM_PLAIN>>>(
        a3, yh2, wt + 2*C*3*C, gates_b + 2*C, nullptr, nullptr, nullptr, nullptr, a1);
    // i = 1
    attn1_kernel<<<dim3(L/128, B), 256>>>(a1, attn1_w + 1*(C/4)*C, attn1_b + (C/4), attn);
    gatesf_kernel<true><<<dim3(L/64, B), 256, GSM_ATTN>>>(
        a1, yh1, wt + 1*C*3*C, gates_b + 1*C, attn, w2t + 32*C, attn2_b + C, yh1, a2);
    // i = 0
    attn1_kernel<<<dim3(L/128, B), 256>>>(a2, attn1_w, attn1_b, attn);
    gatesf_kernel<true><<<dim3(L/64, B), 256, GSM_ATTN>>>(
        a2, yh0, wt, gates_b, attn, w2t, attn2_b, yh0, yl);
}

// round 9
// speedup vs baseline: 1.3586x; 1.0763x over previous
#include <cuda_runtime.h>
#include <math.h>
#include <stdint.h>

#define B 32
#define C 128
#define L 4096
#define NROW (B*C)
#define BCL (B*C*L)            // 16777216
#define FL 9
#define DIM 512
#define NYL ((size_t)BCL)

// ---------------- scratch (device globals; no allocation) ----------------
__device__ float g_a1[BCL];
__device__ float g_a2[BCL];
__device__ float g_a3[BCL];
__device__ float g_attn[B*(C/4)*L];
__device__ float g_feat[3*B*C];          // per-level feature means
__device__ float g_h1[B*DIM];
__device__ float g_h2[B*2*DIM];
__device__ float g_wt[3*C*3*C];          // gates weights [lvl][ci][k][co]
__device__ float g_w2t[2*32*C];          // attn2 weights [lvl][ci][co]

__device__ __forceinline__ float gelu_f(float x){
    return 0.5f*x*(1.0f+erff(x*0.7071067811865476f));
}
__device__ __forceinline__ float sigmoid_f(float x){
    return 1.0f/(1.0f+expf(-x));
}

// ---- packed f32x2 helpers (Blackwell FFMA2) ----
__device__ __forceinline__ unsigned long long pack2(float lo, float hi){
    unsigned long long r;
    asm("mov.b64 %0, {%1, %2};" : "=l"(r) : "f"(lo), "f"(hi));
    return r;
}
__device__ __forceinline__ unsigned long long fma2(unsigned long long a, unsigned long long b, unsigned long long c){
    unsigned long long d;
    asm("fma.rn.f32x2 %0, %1, %2, %3;" : "=l"(d) : "l"(a), "l"(b), "l"(c));
    return d;
}
__device__ __forceinline__ float2 unpack2(unsigned long long v){
    float2 f;
    asm("mov.b64 {%0, %1}, %2;" : "=f"(f.x), "=f"(f.y) : "l"(v));
    return f;
}

// ---------------- mean over L (level 0 only) ----------------
__global__ __launch_bounds__(256) void mean_kernel(const float* __restrict__ x,
                                                   float* __restrict__ feat){
    int row = blockIdx.x;
    const float4* p = (const float4*)(x + (size_t)row*L);
    float s = 0.f;
    for (int i = threadIdx.x; i < L/4; i += 256){
        float4 v = p[i];
        s += (v.x+v.y)+(v.z+v.w);
    }
    __shared__ float red[256];
    red[threadIdx.x] = s; __syncthreads();
    for (int off = 128; off > 0; off >>= 1){
        if (threadIdx.x < off) red[threadIdx.x] += red[threadIdx.x+off];
        __syncthreads();
    }
    if (threadIdx.x == 0) feat[row] = red[0] * (1.0f/(float)L);
}

// ---------------- MLP layers (warp-per-output GEMV) ----------------
__global__ __launch_bounds__(256) void mlp_l1(const float* __restrict__ feat,
                                              const float* __restrict__ sw, const float* __restrict__ sb,
                                              float* __restrict__ h1){
    int b = blockIdx.y;
    int j = blockIdx.x*8 + (threadIdx.x >> 5);
    int lane = threadIdx.x & 31;
    float4 w = ((const float4*)(sw + (size_t)j*C))[lane];
    float4 f = ((const float4*)(feat + b*C))[lane];
    float s = w.x*f.x + w.y*f.y + w.z*f.z + w.w*f.w;
    #pragma unroll
    for (int off = 16; off > 0; off >>= 1) s += __shfl_xor_sync(0xffffffffu, s, off);
    if (lane == 0) h1[b*DIM + j] = gelu_f(s + sb[j]);
}

__global__ __launch_bounds__(256) void mlp_l2(const float* __restrict__ h1,
                                              const float* __restrict__ w1, const float* __restrict__ b1,
                                              float* __restrict__ h2){
    __shared__ __align__(16) float sh[DIM];
    int b = blockIdx.y, t = threadIdx.x;
    for (int i = t; i < DIM/4; i += 256)
        ((float4*)sh)[i] = ((const float4*)(h1 + b*DIM))[i];
    __syncthreads();
    int j = blockIdx.x*8 + (t >> 5);
    int lane = t & 31;
    const float4* wr = (const float4*)(w1 + (size_t)j*DIM);
    float s = 0.f;
    #pragma unroll
    for (int i = 0; i < 4; i++){
        float4 w = wr[i*32 + lane];
        float4 f = ((const float4*)sh)[i*32 + lane];
        s += w.x*f.x + w.y*f.y + w.z*f.z + w.w*f.w;
    }
    #pragma unroll
    for (int off = 16; off > 0; off >>= 1) s += __shfl_xor_sync(0xffffffffu, s, off);
    if (lane == 0) h2[b*2*DIM + j] = gelu_f(s + b1[j]);
}

__global__ __launch_bounds__(576) void mlp_l3(const float* __restrict__ h2,
                                              const float* __restrict__ w2, const float* __restrict__ b2,
                                              float* __restrict__ lo, float* __restrict__ hi){
    __shared__ __align__(16) float sh[2*DIM];
    int b = blockIdx.x, t = threadIdx.x;
    for (int i = t; i < 2*DIM/4; i += 576)
        ((float4*)sh)[i] = ((const float4*)(h2 + b*2*DIM))[i];
    __syncthreads();
    int j = t >> 5, lane = t & 31;     // 18 warps
    const float4* wr = (const float4*)(w2 + (size_t)j*2*DIM);
    float s = 0.f;
    #pragma unroll
    for (int i = 0; i < 8; i++){
        float4 w = wr[i*32 + lane];
        float4 f = ((const float4*)sh)[i*32 + lane];
        s += w.x*f.x + w.y*f.y + w.z*f.z + w.w*f.w;
    }
    #pragma unroll
    for (int off = 16; off > 0; off >>= 1) s += __shfl_xor_sync(0xffffffffu, s, off);
    if (lane == 0){
        float v = s + b2[j];
        if (j < FL) lo[b*FL + j] = v;
        else        hi[b*FL + (j-FL)] = v;
    }
}

// ---------------- ortho loss (last level only) + energy=0 ----------------
__global__ void ortho_kernel(const float* __restrict__ lo, float* __restrict__ out_scalars){
    int b = threadIdx.x;
    float v[FL]; float ss = 0.f;
    #pragma unroll
    for (int k = 0; k < FL; k++){ v[k] = lo[b*FL+k]; ss += v[k]*v[k]; }
    float den = sqrtf(ss) + 1e-8f;
    float S = 0.f, sq = 0.f;
    #pragma unroll
    for (int k = 0; k < FL; k++){
        float n = v[k]/den;
        S  += fabsf(n);
        sq += n*n;
    }
    float S2  = S*S;
    float amp = fabsf(sq - 1.0f);
    float sm  = fabsf(v[0]);
    #pragma unroll
    for (int k = 1; k < FL; k++) sm += fabsf(v[k]-v[k-1]);
    sm += fabsf(v[FL-1]);
    #pragma unroll
    for (int off = 16; off > 0; off >>= 1){
        S2  += __shfl_xor_sync(0xffffffffu, S2,  off);
        amp += __shfl_xor_sync(0xffffffffu, amp, off);
        sm  += __shfl_xor_sync(0xffffffffu, sm,  off);
    }
    if (b == 0){
        float shift  = 3.0f * S2 / (32.0f*81.0f);
        float ampm   = amp / 32.0f;
        float smm    = sm / (32.0f*10.0f);
        out_scalars[0] = 0.01f*(shift + ampm) + 0.1f*smm;
        out_scalars[1] = 0.0f;
    }
}

// ---------------- per-sample depthwise 9-tap (edge pad) + mean accumulate ----------------
#define DTL 1024
__global__ __launch_bounds__(256) void dw_kernel(
    const float* __restrict__ x, const float* __restrict__ lo, const float* __restrict__ hi,
    float* __restrict__ out_a, float* __restrict__ out_d, float* __restrict__ feat_next)
{
    int row = blockIdx.y;
    int b   = row >> 7;
    int l0  = blockIdx.x * DTL;
    __shared__ __align__(16) float s[DTL + 16];
    __shared__ float wsum[8];
    const float* xr = x + (size_t)row * L;
    int t = threadIdx.x, lane = t & 31, wid = t >> 5;
    {
        const float4* xv = (const float4*)(xr + l0);
        ((float4*)(s + 4))[t] = xv[t];
    }
    if (t < 4){
        int li = l0 - 4 + t;
        s[t] = xr[max(li, 0)];
        int ri = l0 + DTL + t;
        s[DTL + 4 + t] = xr[min(ri, L-1)];
    }
    unsigned long long pf[FL];
    #pragma unroll
    for (int k = 0; k < FL; k++) pf[k] = pack2(__ldg(&lo[b*FL+k]), __ldg(&hi[b*FL+k]));
    __syncthreads();

    int i0 = t * 4;
    float win[12];
    #pragma unroll
    for (int j = 0; j < 12; j++) win[j] = s[i0 + j];
    unsigned long long acc[4];
    #pragma unroll
    for (int p = 0; p < 4; p++) acc[p] = 0ull;
    #pragma unroll
    for (int k = 0; k < FL; k++){
        #pragma unroll
        for (int p = 0; p < 4; p++){
            unsigned long long vv = pack2(win[p+k], win[p+k]);
            acc[p] = fma2(vv, pf[k], acc[p]);
        }
    }
    float4 ra, rd;
    float2 f0 = unpack2(acc[0]), f1 = unpack2(acc[1]), f2 = unpack2(acc[2]), f3 = unpack2(acc[3]);
    ra.x = f0.x; ra.y = f1.x; ra.z = f2.x; ra.w = f3.x;
    rd.x = f0.y; rd.y = f1.y; rd.z = f2.y; rd.w = f3.y;
    size_t idx = (size_t)row*L + l0 + i0;
    *(float4*)(out_a + idx) = ra;
    *(float4*)(out_d + idx) = rd;

    if (feat_next){
        float s4 = (ra.x + ra.y) + (ra.z + ra.w);
        #pragma unroll
        for (int off = 16; off > 0; off >>= 1) s4 += __shfl_xor_sync(0xffffffffu, s4, off);
        if (lane == 0) wsum[wid] = s4;
        __syncthreads();
        if (t == 0){
            float tot = 0.f;
            #pragma unroll
            for (int w = 0; w < 8; w++) tot += wsum[w];
            atomicAdd(feat_next + row, tot * (1.0f/(float)L));
        }
    }
}

// ---------------- weight prep ----------------
__global__ void transpose_w_kernel(const float* __restrict__ gw, float* __restrict__ wt){
    int idx = blockIdx.x*256 + threadIdx.x;
    if (idx < 3*C*C*3){
        int lvl = idx / (C*C*3);
        int r   = idx % (C*C*3);
        int ci  = r / (3*C);
        int k   = (r % (3*C)) / C;
        int co  = r % C;
        wt[idx] = gw[(size_t)lvl*C*C*3 + ((size_t)co*C + ci)*3 + k];
    }
}
__global__ void prep2_kernel(const float* __restrict__ attn2_w, float* __restrict__ w2t,
                             float* __restrict__ feat){
    int idx = blockIdx.x*256 + threadIdx.x;
    if (idx < 2*32*C){
        int lvl = idx / (32*C);
        int r   = idx % (32*C);
        int ci  = r >> 7, co = r & 127;
        w2t[idx] = attn2_w[((size_t)lvl*C + co)*32 + ci];
    }
    if (idx < 2*B*C) feat[B*C + idx] = 0.f;   // zero feat levels 1,2
}

// ---------------- fused gates (+ optional attn2), 128-l tiles, 4 l/lane ----------------
// z1 = conv3(cur)+bias; ATTN: z2 = W2*a+b2, det' = det*(1+sig(z2)), yh=det'
// out = cur + sig(z1)*det'
#define P_X 132
#define SO_U  (C*P_X*4)                 // 67584: union region (s_w chunks / s_w2)
#define SO_A  (SO_U + 32*C*4)           // 83968
#define GSM_ATTN  (SO_A + 32*C*4)       // 100352
#define GSM_PLAIN (SO_U + 8*3*C*4)      // 79872

template<bool ATTN>
__global__ __launch_bounds__(256, 2) void gatesf_kernel(
    const float* __restrict__ cur, const float* __restrict__ det_raw,
    const float* __restrict__ wt, const float* __restrict__ bias,
    const float* __restrict__ a, const float* __restrict__ w2t, const float* __restrict__ bias2,
    float* __restrict__ yh_out, float* __restrict__ out)
{
    extern __shared__ __align__(16) char smem[];
    float* s_x  = (float*)smem;              // [ci][132], j=0 <-> l0-1
    float* s_w  = (float*)(smem + SO_U);     // phase2: [8*3][128] chunks
    float* s_w2 = (float*)(smem + SO_U);     // phase1: [32][128]
    float* s_a  = (float*)(smem + SO_A);     // [32][128]
    int l0 = blockIdx.x*128, b = blockIdx.y, t = threadIdx.x;
    int wid = t >> 5, lane = t & 31, co0 = wid*16;
    int lq = lane*4;

    for (int idx = t; idx < C*130; idx += 256){
        int ci = idx/130, j = idx%130;
        int li = l0 + j - 1;
        float v = 0.f;
        if (li >= 0 && li < L) v = cur[((size_t)(b*C+ci))*L + li];
        s_x[ci*P_X + j] = v;
    }
    if (ATTN){
        for (int idx = t; idx < 32*C; idx += 256){
            int ci = idx >> 7, j = idx & 127;
            s_a[idx] = a[((size_t)(b*32+ci))*L + l0 + j];
        }
        for (int idx = t; idx < 32*C; idx += 256) s_w2[idx] = w2t[idx];
    }
    __syncthreads();

    // ---- phase 1 (ATTN): det' = det*(1+sig(W2*a+b2)) -> yh_out ----
    if (ATTN){
        unsigned long long acc2[8][4];
        #pragma unroll
        for (int c = 0; c < 8; c++)
            #pragma unroll
            for (int q = 0; q < 4; q++) acc2[c][q] = 0ull;
        #pragma unroll 4
        for (int ci = 0; ci < 32; ci++){
            float4 xv = *(const float4*)(&s_a[ci*C + lq]);
            unsigned long long p0 = pack2(xv.x, xv.x);
            unsigned long long p1 = pack2(xv.y, xv.y);
            unsigned long long p2 = pack2(xv.z, xv.z);
            unsigned long long p3 = pack2(xv.w, xv.w);
            const ulonglong2* wp = (const ulonglong2*)(&s_w2[ci*C + co0]);
            unsigned long long wr[8];
            ((ulonglong2*)wr)[0] = wp[0];
            ((ulonglong2*)wr)[1] = wp[1];
            ((ulonglong2*)wr)[2] = wp[2];
            ((ulonglong2*)wr)[3] = wp[3];
            #pragma unroll
            for (int c = 0; c < 8; c++){
                acc2[c][0] = fma2(wr[c], p0, acc2[c][0]);
                acc2[c][1] = fma2(wr[c], p1, acc2[c][1]);
                acc2[c][2] = fma2(wr[c], p2, acc2[c][2]);
                acc2[c][3] = fma2(wr[c], p3, acc2[c][3]);
            }
        }
        #pragma unroll
        for (int c = 0; c < 8; c++){
            int co = co0 + 2*c;
            float2 z[4];
            #pragma unroll
            for (int q = 0; q < 4; q++) z[q] = unpack2(acc2[c][q]);
            #pragma unroll
            for (int s = 0; s < 2; s++){
                float bv = __ldg(&bias2[co+s]);
                size_t idx = ((size_t)(b*C+co+s))*L + l0 + lq;
                float4 dv = *(const float4*)(det_raw + idx);
                dv.x *= 1.0f + sigmoid_f((s ? z[0].y : z[0].x) + bv);
                dv.y *= 1.0f + sigmoid_f((s ? z[1].y : z[1].x) + bv);
                dv.z *= 1.0f + sigmoid_f((s ? z[2].y : z[2].x) + bv);
                dv.w *= 1.0f + sigmoid_f((s ? z[3].y : z[3].x) + bv);
                *(float4*)(yh_out + idx) = dv;
            }
        }
    }

    // ---- phase 2: conv3 ----
    unsigned long long acc[8][4];
    #pragma unroll
    for (int c = 0; c < 8; c++)
        #pragma unroll
        for (int q = 0; q < 4; q++) acc[c][q] = 0ull;

    for (int ci0 = 0; ci0 < C; ci0 += 8){
        __syncthreads();
        for (int idx = t; idx < 8*3*C; idx += 256) s_w[idx] = wt[ci0*3*C + idx];
        __syncthreads();
        #pragma unroll
        for (int ci = 0; ci < 8; ci++){
            const float* xr = &s_x[(ci0+ci)*P_X + lq];
            float4 xv = *(const float4*)xr;
            float x4 = xr[4], x5 = xr[5];
            unsigned long long p[6];
            p[0] = pack2(xv.x, xv.x);
            p[1] = pack2(xv.y, xv.y);
            p[2] = pack2(xv.z, xv.z);
            p[3] = pack2(xv.w, xv.w);
            p[4] = pack2(x4, x4);
            p[5] = pack2(x5, x5);
            #pragma unroll
            for (int tap = 0; tap < 3; tap++){
                const ulonglong2* wp = (const ulonglong2*)(&s_w[(ci*3+tap)*C + co0]);
                unsigned long long wr[8];
                ((ulonglong2*)wr)[0] = wp[0];
                ((ulonglong2*)wr)[1] = wp[1];
                ((ulonglong2*)wr)[2] = wp[2];
                ((ulonglong2*)wr)[3] = wp[3];
                #pragma unroll
                for (int c = 0; c < 8; c++){
                    acc[c][0] = fma2(wr[c], p[tap],   acc[c][0]);
                    acc[c][1] = fma2(wr[c], p[tap+1], acc[c][1]);
                    acc[c][2] = fma2(wr[c], p[tap+2], acc[c][2]);
                    acc[c][3] = fma2(wr[c], p[tap+3], acc[c][3]);
                }
            }
        }
    }

    // ---- epilogue ----
    #pragma unroll
    for (int c = 0; c < 8; c++){
        int co = co0 + 2*c;
        float2 z[4];
        #pragma unroll
        for (int q = 0; q < 4; q++) z[q] = unpack2(acc[c][q]);
        #pragma unroll
        for (int s = 0; s < 2; s++){
            float bv = __ldg(&bias[co+s]);
            size_t idx = ((size_t)(b*C+co+s))*L + l0 + lq;
            const float* dsrc = ATTN ? yh_out : det_raw;
            float4 dv = *(const float4*)(dsrc + idx);
            const float* cr = &s_x[(co+s)*P_X + lq + 1];
            float4 ov;
            ov.x = cr[0] + sigmoid_f((s ? z[0].y : z[0].x) + bv)*dv.x;
            ov.y = cr[1] + sigmoid_f((s ? z[1].y : z[1].x) + bv)*dv.y;
            ov.z = cr[2] + sigmoid_f((s ? z[2].y : z[2].x) + bv)*dv.z;
            ov.w = cr[3] + sigmoid_f((s ? z[3].y : z[3].x) + bv)*dv.w;
            *(float4*)(out + idx) = ov;
        }
    }
}

// ---------------- attn1: 1x1 conv 128->32 + gelu (FFMA2) ----------------
__global__ __launch_bounds__(256) void attn1_kernel(
    const float* __restrict__ cur, const float* __restrict__ w,
    const float* __restrict__ bias, float* __restrict__ outa)
{
    __shared__ __align__(16) float s_x[32*128];
    __shared__ __align__(16) float s_w[128*32];
    int b = blockIdx.y, l0 = blockIdx.x*128, t = threadIdx.x;
    for (int idx = t; idx < C*32; idx += 256){
        int ci = idx >> 5, co = idx & 31;
        s_w[idx] = w[co*C + ci];
    }
    int wid = t >> 5, lane = t & 31, co0 = wid*4;
    unsigned long long acc[2][4];
    #pragma unroll
    for (int c = 0; c < 2; c++)
        #pragma unroll
        for (int j = 0; j < 4; j++) acc[c][j] = 0ull;

    for (int ci0 = 0; ci0 < C; ci0 += 32){
        __syncthreads();
        for (int idx = t; idx < 32*128; idx += 256){
            int ci = idx >> 7, l = idx & 127;
            s_x[idx] = cur[((size_t)(b*C + ci0 + ci))*L + l0 + l];
        }
        __syncthreads();
        #pragma unroll 4
        for (int ci = 0; ci < 32; ci++){
            unsigned long long wr[2];
            wr[0] = *(const unsigned long long*)(&s_w[(ci0+ci)*32 + co0]);
            wr[1] = *(const unsigned long long*)(&s_w[(ci0+ci)*32 + co0 + 2]);
            #pragma unroll
            for (int j = 0; j < 4; j++){
                float xv = s_x[ci*128 + lane + j*32];
                unsigned long long p = pack2(xv, xv);
                acc[0][j] = fma2(wr[0], p, acc[0][j]);
                acc[1][j] = fma2(wr[1], p, acc[1][j]);
            }
        }
    }
    #pragma unroll
    for (int c = 0; c < 2; c++){
        int co = co0 + 2*c;
        float b0 = bias[co], b1 = bias[co+1];
        #pragma unroll
        for (int j = 0; j < 4; j++){
            float2 f = unpack2(acc[c][j]);
            size_t idx0 = ((size_t)(b*32 + co))*L + l0 + lane + j*32;
            outa[idx0]     = gelu_f(f.x + b0);
            outa[idx0 + L] = gelu_f(f.y + b1);
        }
    }
}

// ---------------- host launch ----------------
extern "C" void kernel_launch(void* const* d_in, const int* in_sizes, int n_in,
                              void* d_out, int out_size)
{
    const float* x       = (const float*)d_in[0];
    const float* stat_w  = (const float*)d_in[1];
    const float* stat_b  = (const float*)d_in[2];
    const float* wg1_w   = (const float*)d_in[3];
    const float* wg1_b   = (const float*)d_in[4];
    const float* wg2_w   = (const float*)d_in[5];
    const float* wg2_b   = (const float*)d_in[6];
    const float* gates_w = (const float*)d_in[7];
    const float* gates_b = (const float*)d_in[8];
    const float* attn1_w = (const float*)d_in[9];
    const float* attn1_b = (const float*)d_in[10];
    const float* attn2_w = (const float*)d_in[11];
    const float* attn2_b = (const float*)d_in[12];
    float* out = (float*)d_out;

    float *a1, *a2, *a3, *attn, *feat, *h1, *h2, *wt, *w2t;
    cudaGetSymbolAddress((void**)&a1,   g_a1);
    cudaGetSymbolAddress((void**)&a2,   g_a2);
    cudaGetSymbolAddress((void**)&a3,   g_a3);
    cudaGetSymbolAddress((void**)&attn, g_attn);
    cudaGetSymbolAddress((void**)&feat, g_feat);
    cudaGetSymbolAddress((void**)&h1,   g_h1);
    cudaGetSymbolAddress((void**)&h2,   g_h2);
    cudaGetSymbolAddress((void**)&wt,   g_wt);
    cudaGetSymbolAddress((void**)&w2t,  g_w2t);

    float* yl  = out;
    float* yh0 = out + NYL;
    float* yh1 = out + 2*NYL;
    float* yh2 = out + 3*NYL;
    float* scal= out + 4*NYL;
    float* lo_all = out + 4*NYL + 2;
    float* hi_all = lo_all + 3*B*FL;

    cudaFuncSetAttribute(gatesf_kernel<true>,  cudaFuncAttributeMaxDynamicSharedMemorySize, GSM_ATTN);
    cudaFuncSetAttribute(gatesf_kernel<false>, cudaFuncAttributeMaxDynamicSharedMemorySize, GSM_PLAIN);

    transpose_w_kernel<<<(3*C*C*3 + 255)/256, 256>>>(gates_w, wt);
    prep2_kernel<<<(2*32*C + 255)/256, 256>>>(attn2_w, w2t, feat);

    const float* ain[3]  = {x, a1, a2};
    float*       aout[3] = {a1, a2, a3};
    float*       dets[3] = {yh0, yh1, yh2};

    mean_kernel<<<NROW, 256>>>(x, feat);
    for (int lvl = 0; lvl < 3; lvl++){
        float* lo = lo_all + lvl*B*FL;
        float* hi = hi_all + lvl*B*FL;
        const float* f = feat + lvl*B*C;
        mlp_l1<<<dim3(DIM/8, B), 256>>>(f, stat_w, stat_b, h1);
        mlp_l2<<<dim3(2*DIM/8, B), 256>>>(h1, wg1_w, wg1_b, h2);
        mlp_l3<<<B, 576>>>(h2, wg2_w, wg2_b, lo, hi);
        float* fnext = (lvl < 2) ? (feat + (lvl+1)*B*C) : nullptr;
        dw_kernel<<<dim3(L/DTL, NROW), 256>>>(ain[lvl], lo, hi, aout[lvl], dets[lvl], fnext);
    }

    ortho_kernel<<<1, 32>>>(lo_all + 2*B*FL, scal);

    // reconstruction: i = 2 (no attn)
    gatesf_kernel<false><<<dim3(L/128, B), 256, GSM_PLAIN>>>(
        a3, yh2, wt + 2*C*3*C, gates_b + 2*C, nullptr, nullptr, nullptr, nullptr, a1);
    // i = 1
    attn1_kernel<<<dim3(L/128, B), 256>>>(a1, attn1_w + 1*(C/4)*C, attn1_b + (C/4), attn);
    gatesf_kernel<true><<<dim3(L/128, B), 256, GSM_ATTN>>>(
        a1, yh1, wt + 1*C*3*C, gates_b + 1*C, attn, w2t + 32*C, attn2_b + C, yh1, a2);
    // i = 0
    attn1_kernel<<<dim3(L/128, B), 256>>>(a2, attn1_w, attn1_b, attn);
    gatesf_kernel<true><<<dim3(L/128, B), 256, GSM_ATTN>>>(
        a2, yh0, wt, gates_b, attn, w2t, attn2_b, yh0, yl);
}